// round 1
// baseline (speedup 1.0000x reference)
#include <cuda_runtime.h>
#include <math.h>
#include <stdint.h>

#define BSZ   1024
#define NP    256
#define DIM   128

// ---------------- scratch (static device globals; no allocation) ------------
__device__ float  g_lh[NP * DIM];    // poincare-mapped lcas, row-major
__device__ float  g_lhT[DIM * NP];   // transposed for coalesced dist loads
__device__ float  g_y2[NP];          // ||lh||^2 per proxy
__device__ float  g_Dz[BSZ * NP];    // dist(z_s, lh)
__device__ float  g_Dt[BSZ * NP];    // dist(t_s, lh)
__device__ float  g_Dll[NP * NP];    // dist(lh, lh)
__device__ double g_accum;           // loss accumulator (fp64)

// ---------------- kernels ---------------------------------------------------
__global__ void k_zero() { g_accum = 0.0; }

// to_poincare(lcas): clip to radius 2.3, expmap0, project. One block per row,
// 128 threads (one per dim), shared tree reductions for the three norms.
__global__ void k_poincare(const float* __restrict__ lcas) {
    const int r = blockIdx.x;
    const int d = threadIdx.x;
    __shared__ float red[DIM];

    float x = lcas[r * DIM + d];

    // norm of raw row
    red[d] = x * x; __syncthreads();
    #pragma unroll
    for (int s = 64; s > 0; s >>= 1) { if (d < s) red[d] += red[d + s]; __syncthreads(); }
    float xn = sqrtf(red[0]) + 1e-5f;
    __syncthreads();

    x *= fminf(1.0f, 2.3f / xn);

    // norm of clipped row
    red[d] = x * x; __syncthreads();
    #pragma unroll
    for (int s = 64; s > 0; s >>= 1) { if (d < s) red[d] += red[d + s]; __syncthreads(); }
    float xn2 = fmaxf(sqrtf(red[0]), 1e-5f);
    __syncthreads();

    const float sqrt_c = 0.31622776601683794f;   // sqrt(0.1)
    float arg = sqrt_c * xn2;
    x = tanhf(arg) * x / arg;                    // expmap0

    // project (no-op in practice: tanh < 0.999, but follow the formula)
    red[d] = x * x; __syncthreads();
    #pragma unroll
    for (int s = 64; s > 0; s >>= 1) { if (d < s) red[d] += red[d + s]; __syncthreads(); }
    float n3 = fmaxf(sqrtf(red[0]), 1e-5f);
    __syncthreads();
    const float maxn = (1.0f - 1e-3f) / 0.31622776601683794f;
    if (n3 > maxn) x = x / n3 * maxn;

    // y^2 of final row
    red[d] = x * x; __syncthreads();
    #pragma unroll
    for (int s = 64; s > 0; s >>= 1) { if (d < s) red[d] += red[d + s]; __syncthreads(); }

    g_lh[r * DIM + d]  = x;
    g_lhT[d * NP + r]  = x;
    if (d == 0) g_y2[r] = red[0];
    __syncthreads();
}

// dist(x_row, lh_col) for all 256 cols. One block per x row, thread = column.
// mode: 0 -> g_Dz, 1 -> g_Dt, 2 -> g_Dll (x taken from g_lh when xin==nullptr).
__global__ void k_dist(const float* __restrict__ xin, int mode) {
    const int row = blockIdx.x;
    const int col = threadIdx.x;      // 256 threads
    float* __restrict__ out = (mode == 0) ? g_Dz : (mode == 1) ? g_Dt : g_Dll;
    const float* __restrict__ X = xin ? xin : g_lh;

    __shared__ float xs[DIM];
    if (col < DIM) xs[col] = X[row * DIM + col];
    __syncthreads();

    float x2 = 0.0f, dot = 0.0f;
    #pragma unroll 16
    for (int d = 0; d < DIM; ++d) {
        float xv = xs[d];
        x2  = fmaf(xv, xv, x2);
        dot = fmaf(xv, g_lhT[d * NP + col], dot);
    }
    const float y2 = g_y2[col];

    const float c = 0.1f;
    float xy    = -dot;                                    // (-x).y
    float a     = 1.0f + 2.0f * c * xy + c * y2;
    float b     = 1.0f - c * x2;
    float denom = 1.0f + 2.0f * c * xy + (c * c) * x2 * y2;
    float numsq = a * a * x2 + 2.0f * a * b * xy + b * b * y2;
    float nrm   = sqrtf(fmaxf(numsq, 1e-12f)) / fabsf(denom + 1e-5f);

    float v = 0.31622776601683794f * nrm;                  // sqrt_c * norm
    v = fminf(fmaxf(v, -0.99999f), 0.99999f);              // artanh clip
    float art = 0.5f * (log1pf(v) - log1pf(-v));
    out[row * NP + col] = 6.324555320336759f * art;        // (2/sqrt_c)*artanh
}

// ghhc: one warp per triplet. Each lane owns 8 contiguous proxies.
// whichD: 0 -> g_Dz, 1 -> g_Dll, 2 -> g_Dt
__global__ void k_ghhc(int whichD, const int* __restrict__ trip,
                       const float* __restrict__ g, int T, double invT) {
    const float* __restrict__ D =
        (whichD == 0) ? g_Dz : (whichD == 1) ? g_Dll : g_Dt;

    __shared__ double warpsum[8];
    const int warp = threadIdx.x >> 5;
    const int lane = threadIdx.x & 31;
    const int t = blockIdx.x * 8 + warp;

    double hc = 0.0;
    if (t < T) {
        const int i = trip[t];
        const int j = trip[T + t];
        const int k = trip[2 * T + t];
        const float* __restrict__ di = D + (size_t)i * NP;
        const float* __restrict__ dj = D + (size_t)j * NP;
        const float* __restrict__ dk = D + (size_t)k * NP;
        const float* __restrict__ g0 = g + (size_t)t * NP;
        const float* __restrict__ g1 = g + ((size_t)T + t) * NP;

        const int base = lane * 8;
        float4 a0 = *(const float4*)(di + base), a1 = *(const float4*)(di + base + 4);
        float4 b0 = *(const float4*)(dj + base), b1 = *(const float4*)(dj + base + 4);
        float4 c0 = *(const float4*)(dk + base), c1 = *(const float4*)(dk + base + 4);
        float4 e0 = *(const float4*)(g0 + base), e1 = *(const float4*)(g0 + base + 4);
        float4 f0 = *(const float4*)(g1 + base), f1 = *(const float4*)(g1 + base + 4);

        float dv[8]  = {a0.x, a0.y, a0.z, a0.w, a1.x, a1.y, a1.z, a1.w};
        float jv[8]  = {b0.x, b0.y, b0.z, b0.w, b1.x, b1.y, b1.z, b1.w};
        float kv[8]  = {c0.x, c0.y, c0.z, c0.w, c1.x, c1.y, c1.z, c1.w};
        float g0v[8] = {e0.x, e0.y, e0.z, e0.w, e1.x, e1.y, e1.z, e1.w};
        float g1v[8] = {f0.x, f0.y, f0.z, f0.w, f1.x, f1.y, f1.z, f1.w};

        float best0 = -INFINITY, best1 = -INFINITY;
        int   idx0 = 0, idx1 = 0;
        #pragma unroll
        for (int u = 0; u < 8; ++u) {
            float m  = fmaxf(dv[u], jv[u]);           // max(di, dj)
            float s0 = g0v[u] + (-m) / 0.1f;          // logits + gumbel
            if (s0 > best0) { best0 = s0; idx0 = base + u; }
            float m2 = fmaxf(kv[u], m);               // max(dk, max_ij)
            float s1 = g1v[u] + (-m2) / 0.1f;
            if (s1 > best1) { best1 = s1; idx1 = base + u; }
        }
        // warp argmax reduce, first-occurrence (lowest index) wins ties
        #pragma unroll
        for (int off = 16; off > 0; off >>= 1) {
            float ov = __shfl_down_sync(0xffffffffu, best0, off);
            int   oi = __shfl_down_sync(0xffffffffu, idx0,  off);
            if (ov > best0 || (ov == best0 && oi < idx0)) { best0 = ov; idx0 = oi; }
            float ow = __shfl_down_sync(0xffffffffu, best1, off);
            int   oj = __shfl_down_sync(0xffffffffu, idx1,  off);
            if (ow > best1 || (ow == best1 && oj < idx1)) { best1 = ow; idx1 = oj; }
        }
        if (lane == 0 && idx0 != idx1) {              // diff_lca gate
            float dia = di[idx0], dib = di[idx1];
            float dja = dj[idx0], djb = dj[idx1];
            float dka = dk[idx0], dkb = dk[idx1];
            float h = fmaxf(dia - dib + 0.1f, 0.0f)
                    + fmaxf(dja - djb + 0.1f, 0.0f)
                    + fmaxf(dkb - dka + 0.1f, 0.0f);
            hc = (double)h * invT;
        }
    }
    if (lane == 0) warpsum[warp] = hc;
    __syncthreads();
    if (threadIdx.x == 0) {
        double s = 0.0;
        #pragma unroll
        for (int w = 0; w < 8; ++w) s += warpsum[w];
        atomicAdd(&g_accum, s);
    }
}

__global__ void k_final(float* __restrict__ out) { out[0] = (float)g_accum; }

// ---------------- launch -----------------------------------------------------
extern "C" void kernel_launch(void* const* d_in, const int* in_sizes, int n_in,
                              void* d_out, int out_size) {
    const float* z_s   = (const float*)d_in[0];
    const float* t_s   = (const float*)d_in[1];
    /* d_in[2] = y, unused */
    const float* lcas  = (const float*)d_in[3];
    const int*   trip1 = (const int*)d_in[4];
    const int*   trip2 = (const int*)d_in[5];
    const int*   trip3 = (const int*)d_in[6];
    const int*   trip4 = (const int*)d_in[7];
    const float* g1    = (const float*)d_in[8];
    const float* g2    = (const float*)d_in[9];
    const float* g3    = (const float*)d_in[10];
    const float* g4    = (const float*)d_in[11];

    const int T1 = in_sizes[4] / 3;   // 51200
    const int T2 = in_sizes[5] / 3;   // 12800
    const int T3 = in_sizes[6] / 3;   // 51200
    const int T4 = in_sizes[7] / 3;   // 12800

    k_zero<<<1, 1>>>();
    k_poincare<<<NP, DIM>>>(lcas);
    k_dist<<<BSZ, NP>>>(z_s, 0);
    k_dist<<<BSZ, NP>>>(t_s, 1);
    k_dist<<<NP, NP>>>(nullptr, 2);   // lh vs lh

    k_ghhc<<<(T1 + 7) / 8, 256>>>(0, trip1, g1, T1, 1.0 / (double)T1);
    k_ghhc<<<(T2 + 7) / 8, 256>>>(1, trip2, g2, T2, 1.0 / (double)T2);
    k_ghhc<<<(T3 + 7) / 8, 256>>>(2, trip3, g3, T3, 1.0 / (double)T3);
    k_ghhc<<<(T4 + 7) / 8, 256>>>(1, trip4, g4, T4, 1.0 / (double)T4);

    k_final<<<1, 1>>>((float*)d_out);
}

// round 2
// speedup vs baseline: 1.2385x; 1.2385x over previous
#include <cuda_runtime.h>
#include <math.h>
#include <stdint.h>

#define BSZ   1024
#define NP    256
#define DIM   128
#define TB    51200      // triplets per batch segment (T1 == T3)
#define TL    12800      // triplets per lca segment   (T2 == T4)
#define TTOT  (2*TB + 2*TL)

// ---------------- scratch (static device globals; no allocation) ------------
__device__ float  g_lh[NP * DIM];    // poincare-mapped lcas, row-major
__device__ float  g_lhT[DIM * NP];   // transposed for coalesced dist loads
__device__ float  g_y2[NP];          // ||lh||^2 per proxy
__device__ float  g_Dz[BSZ * NP];    // dist(z_s, lh)
__device__ float  g_Dt[BSZ * NP];    // dist(t_s, lh)
__device__ float  g_Dll[NP * NP];    // dist(lh, lh)
__device__ double g_accum;           // loss accumulator (fp64)

// ---------------- to_poincare (also zeroes the accumulator) -----------------
__global__ void k_poincare(const float* __restrict__ lcas) {
    const int r = blockIdx.x;
    const int d = threadIdx.x;
    if (r == 0 && d == 0) g_accum = 0.0;
    __shared__ float red[DIM];

    float x = lcas[r * DIM + d];

    red[d] = x * x; __syncthreads();
    #pragma unroll
    for (int s = 64; s > 0; s >>= 1) { if (d < s) red[d] += red[d + s]; __syncthreads(); }
    float xn = sqrtf(red[0]) + 1e-5f;
    __syncthreads();

    x *= fminf(1.0f, 2.3f / xn);

    red[d] = x * x; __syncthreads();
    #pragma unroll
    for (int s = 64; s > 0; s >>= 1) { if (d < s) red[d] += red[d + s]; __syncthreads(); }
    float xn2 = fmaxf(sqrtf(red[0]), 1e-5f);
    __syncthreads();

    const float sqrt_c = 0.31622776601683794f;   // sqrt(0.1)
    float arg = sqrt_c * xn2;
    x = tanhf(arg) * x / arg;                    // expmap0

    red[d] = x * x; __syncthreads();
    #pragma unroll
    for (int s = 64; s > 0; s >>= 1) { if (d < s) red[d] += red[d + s]; __syncthreads(); }
    float n3 = fmaxf(sqrtf(red[0]), 1e-5f);
    __syncthreads();
    const float maxn = (1.0f - 1e-3f) / 0.31622776601683794f;
    if (n3 > maxn) x = x / n3 * maxn;

    red[d] = x * x; __syncthreads();
    #pragma unroll
    for (int s = 64; s > 0; s >>= 1) { if (d < s) red[d] += red[d + s]; __syncthreads(); }

    g_lh[r * DIM + d]  = x;
    g_lhT[d * NP + r]  = x;
    if (d == 0) g_y2[r] = red[0];
}

// ---------------- fused distance matrices -----------------------------------
// 8 source rows per block, 256 threads (one per proxy column).
// blocks: [0,128) -> z rows, [128,256) -> t rows, [256,288) -> lh rows.
__global__ __launch_bounds__(256) void k_dist_all(const float* __restrict__ z,
                                                  const float* __restrict__ t) {
    __shared__ float xs[8 * DIM];
    __shared__ float sx2[8];
    const int b   = blockIdx.x;
    const int tid = threadIdx.x;

    const float* __restrict__ X;
    float* __restrict__ out;
    int r0;
    if (b < 128)      { X = z;    out = g_Dz;  r0 = b * 8; }
    else if (b < 256) { X = t;    out = g_Dt;  r0 = (b - 128) * 8; }
    else              { X = g_lh; out = g_Dll; r0 = (b - 256) * 8; }

    #pragma unroll
    for (int idx = tid; idx < 8 * DIM; idx += 256)
        xs[idx] = X[r0 * DIM + idx];
    __syncthreads();

    // per-row squared norm: warp w reduces row w
    const int warp = tid >> 5, lane = tid & 31;
    {
        float s = 0.0f;
        #pragma unroll
        for (int q = 0; q < 4; ++q) {
            float e = xs[warp * DIM + lane + 32 * q];
            s = fmaf(e, e, s);
        }
        #pragma unroll
        for (int off = 16; off > 0; off >>= 1)
            s += __shfl_down_sync(0xffffffffu, s, off);
        if (lane == 0) sx2[warp] = s;
    }
    __syncthreads();

    const int col = tid;
    float acc[8] = {0,0,0,0,0,0,0,0};
    #pragma unroll 4
    for (int d = 0; d < DIM; ++d) {
        float yv = g_lhT[d * NP + col];
        #pragma unroll
        for (int r = 0; r < 8; ++r)
            acc[r] = fmaf(xs[r * DIM + d], yv, acc[r]);
    }

    const float y2 = g_y2[col];
    const float c  = 0.1f;
    #pragma unroll
    for (int r = 0; r < 8; ++r) {
        float x2    = sx2[r];
        float xy    = -acc[r];                               // (-x).y
        float a     = 1.0f + 2.0f * c * xy + c * y2;
        float bb    = 1.0f - c * x2;
        float denom = 1.0f + 2.0f * c * xy + (c * c) * x2 * y2;
        float numsq = a * a * x2 + 2.0f * a * bb * xy + bb * bb * y2;
        float nrm   = sqrtf(fmaxf(numsq, 1e-12f)) / fabsf(denom + 1e-5f);
        float v = 0.31622776601683794f * nrm;
        v = fminf(fmaxf(v, -0.99999f), 0.99999f);
        float art = 0.5f * (log1pf(v) - log1pf(-v));
        out[(r0 + r) * NP + col] = 6.324555320336759f * art;
    }
}

// ---------------- fused ghhc over all 4 triplet sets -------------------------
// One warp per triplet; lane owns 8 contiguous proxies. Phase-split to keep
// register liveness low (only m[8] crosses phases).
__global__ __launch_bounds__(256, 4) void k_ghhc_all(
    const int*  __restrict__ t1, const int*  __restrict__ t2,
    const int*  __restrict__ t3, const int*  __restrict__ t4,
    const float* __restrict__ G1, const float* __restrict__ G2,
    const float* __restrict__ G3, const float* __restrict__ G4) {
    __shared__ double wsum[8];
    const int warp = threadIdx.x >> 5;
    const int lane = threadIdx.x & 31;
    const int w    = blockIdx.x * 8 + warp;

    const int* trip; const float* g; const float* D; int T, t; double invT;
    if (w < TB)                { trip = t1; g = G1; D = g_Dz;  T = TB; t = w;                 invT = 1.0 / TB; }
    else if (w < TB + TL)      { trip = t2; g = G2; D = g_Dll; T = TL; t = w - TB;            invT = 1.0 / TL; }
    else if (w < 2*TB + TL)    { trip = t3; g = G3; D = g_Dt;  T = TB; t = w - (TB + TL);     invT = 1.0 / TB; }
    else                       { trip = t4; g = G4; D = g_Dll; T = TL; t = w - (2*TB + TL);   invT = 1.0 / TL; }

    const int i = trip[t];
    const int j = trip[T + t];
    const int k = trip[2 * T + t];
    const float* __restrict__ di = D + (size_t)i * NP;
    const float* __restrict__ dj = D + (size_t)j * NP;
    const float* __restrict__ dk = D + (size_t)k * NP;
    const float* __restrict__ g0 = g + (size_t)t * NP;
    const float* __restrict__ g1 = g + ((size_t)T + t) * NP;
    const int base = lane * 8;

    float m[8];
    float best0 = -INFINITY, best1 = -INFINITY;
    int   idx0 = 0, idx1 = 0;

    // ---- phase A: di, dj, g0 -> max_ij, score0 ----
    {
        float4 a0 = *(const float4*)(di + base), a1 = *(const float4*)(di + base + 4);
        float4 b0 = *(const float4*)(dj + base), b1 = *(const float4*)(dj + base + 4);
        float4 e0 = *(const float4*)(g0 + base), e1 = *(const float4*)(g0 + base + 4);
        float av[8] = {a0.x, a0.y, a0.z, a0.w, a1.x, a1.y, a1.z, a1.w};
        float bv[8] = {b0.x, b0.y, b0.z, b0.w, b1.x, b1.y, b1.z, b1.w};
        float ev[8] = {e0.x, e0.y, e0.z, e0.w, e1.x, e1.y, e1.z, e1.w};
        #pragma unroll
        for (int u = 0; u < 8; ++u) {
            m[u] = fmaxf(av[u], bv[u]);
            float s0 = fmaf(m[u], -10.0f, ev[u]);     // g - max/tau
            if (s0 > best0) { best0 = s0; idx0 = base + u; }
        }
    }
    // ---- phase B: dk, g1 -> max_ijk, score1 ----
    {
        float4 c0 = *(const float4*)(dk + base), c1 = *(const float4*)(dk + base + 4);
        float4 f0 = *(const float4*)(g1 + base), f1 = *(const float4*)(g1 + base + 4);
        float cv[8] = {c0.x, c0.y, c0.z, c0.w, c1.x, c1.y, c1.z, c1.w};
        float fv[8] = {f0.x, f0.y, f0.z, f0.w, f1.x, f1.y, f1.z, f1.w};
        #pragma unroll
        for (int u = 0; u < 8; ++u) {
            float m2 = fmaxf(cv[u], m[u]);
            float s1 = fmaf(m2, -10.0f, fv[u]);
            if (s1 > best1) { best1 = s1; idx1 = base + u; }
        }
    }

    // warp argmax reduce, first-occurrence (lowest index) wins ties
    #pragma unroll
    for (int off = 16; off > 0; off >>= 1) {
        float ov = __shfl_down_sync(0xffffffffu, best0, off);
        int   oi = __shfl_down_sync(0xffffffffu, idx0,  off);
        if (ov > best0 || (ov == best0 && oi < idx0)) { best0 = ov; idx0 = oi; }
        float ow = __shfl_down_sync(0xffffffffu, best1, off);
        int   oj = __shfl_down_sync(0xffffffffu, idx1,  off);
        if (ow > best1 || (ow == best1 && oj < idx1)) { best1 = ow; idx1 = oj; }
    }

    double hc = 0.0;
    if (lane == 0 && idx0 != idx1) {              // diff_lca gate
        float dia = di[idx0], dib = di[idx1];
        float dja = dj[idx0], djb = dj[idx1];
        float dka = dk[idx0], dkb = dk[idx1];
        float h = fmaxf(dia - dib + 0.1f, 0.0f)
                + fmaxf(dja - djb + 0.1f, 0.0f)
                + fmaxf(dkb - dka + 0.1f, 0.0f);
        hc = (double)h * invT;
    }
    if (lane == 0) wsum[warp] = hc;
    __syncthreads();
    if (threadIdx.x == 0) {
        double s = 0.0;
        #pragma unroll
        for (int q = 0; q < 8; ++q) s += wsum[q];
        atomicAdd(&g_accum, s);
    }
}

__global__ void k_final(float* __restrict__ out) { out[0] = (float)g_accum; }

// ---------------- launch -----------------------------------------------------
extern "C" void kernel_launch(void* const* d_in, const int* in_sizes, int n_in,
                              void* d_out, int out_size) {
    const float* z_s   = (const float*)d_in[0];
    const float* t_s   = (const float*)d_in[1];
    /* d_in[2] = y, unused */
    const float* lcas  = (const float*)d_in[3];
    const int*   trip1 = (const int*)d_in[4];
    const int*   trip2 = (const int*)d_in[5];
    const int*   trip3 = (const int*)d_in[6];
    const int*   trip4 = (const int*)d_in[7];
    const float* g1    = (const float*)d_in[8];
    const float* g2    = (const float*)d_in[9];
    const float* g3    = (const float*)d_in[10];
    const float* g4    = (const float*)d_in[11];

    k_poincare<<<NP, DIM>>>(lcas);
    k_dist_all<<<288, 256>>>(z_s, t_s);
    k_ghhc_all<<<TTOT / 8, 256>>>(trip1, trip2, trip3, trip4, g1, g2, g3, g4);
    k_final<<<1, 1>>>((float*)d_out);
}